// round 6
// baseline (speedup 1.0000x reference)
#include <cuda_runtime.h>
#include <math.h>

#define NN 1024
#define NT 256
#define BB 32

typedef unsigned long long u64;

// ---------------- device scratch ----------------
__device__ float2   g_pa[BB * NN];
__device__ float2   g_pam[BB * NN];
__device__ float2   g_tw[512];            // W_1024^k
__device__ double   g_accS[BB], g_accST[BB], g_accT[BB], g_accT2[BB];
__device__ unsigned g_accMax[BB];
__device__ float    g_mse[BB];

__device__ __forceinline__ float2 cmulf(float2 a, float2 b) {
    return make_float2(a.x * b.x - a.y * b.y, a.x * b.y + a.y * b.x);
}

// ---------------- packed f32x2 helpers ----------------
__device__ __forceinline__ u64 pk2(float lo, float hi) {
    u64 r; asm("mov.b64 %0,{%1,%2};" : "=l"(r) : "f"(lo), "f"(hi)); return r;
}
__device__ __forceinline__ void upk2(u64 v, float& lo, float& hi) {
    asm("mov.b64 {%0,%1},%2;" : "=f"(lo), "=f"(hi) : "l"(v));
}
__device__ __forceinline__ u64 padd(u64 a, u64 b) {
    u64 r; asm("add.rn.f32x2 %0,%1,%2;" : "=l"(r) : "l"(a), "l"(b)); return r;
}
__device__ __forceinline__ u64 pmul(u64 a, u64 b) {
    u64 r; asm("mul.rn.f32x2 %0,%1,%2;" : "=l"(r) : "l"(a), "l"(b)); return r;
}
__device__ __forceinline__ u64 pfma(u64 a, u64 b, u64 c) {
    u64 r; asm("fma.rn.f32x2 %0,%1,%2,%3;" : "=l"(r) : "l"(a), "l"(b), "l"(c)); return r;
}
__device__ __forceinline__ u64 psub(u64 a, u64 b) {
    const u64 n1 = 0xBF800000BF800000ULL;  // (-1.0f, -1.0f)
    u64 r; asm("fma.rn.f32x2 %0,%1,%2,%3;" : "=l"(r) : "l"(b), "l"(n1), "l"(a)); return r;
}

struct PTw { u64 re, im, imn; };
__device__ __forceinline__ PTw mkptw(float2 w) {
    PTw t; t.re = pk2(w.x, w.x); t.im = pk2(w.y, w.y); t.imn = pk2(-w.y, -w.y); return t;
}
__device__ __forceinline__ void pcmul(u64& re, u64& im, const PTw& tw) {
    u64 nim = pfma(im, tw.re, pmul(re, tw.im));
    u64 nre = pfma(im, tw.imn, pmul(re, tw.re));
    re = nre; im = nim;
}

#define PBFLY4(i0, i1, i2, i3, T1, T2, T3) do {                               \
    u64 t0r = padd(Rr[i0], Rr[i2]), t0i = padd(Ri[i0], Ri[i2]);               \
    u64 t1r = psub(Rr[i0], Rr[i2]), t1i = psub(Ri[i0], Ri[i2]);               \
    u64 t2r = padd(Rr[i1], Rr[i3]), t2i = padd(Ri[i1], Ri[i3]);               \
    u64 t3r = psub(Rr[i1], Rr[i3]), t3i = psub(Ri[i1], Ri[i3]);               \
    Rr[i0] = padd(t0r, t2r); Ri[i0] = padd(t0i, t2i);                         \
    { u64 br = padd(t1r, t3i), bi = psub(t1i, t3r); pcmul(br, bi, T1);        \
      Rr[i1] = br; Ri[i1] = bi; }                                             \
    { u64 cr = psub(t0r, t2r), ci = psub(t0i, t2i); pcmul(cr, ci, T2);        \
      Rr[i2] = cr; Ri[i2] = ci; }                                             \
    { u64 dr = psub(t1r, t3i), di = padd(t1i, t3r); pcmul(dr, di, T3);        \
      Rr[i3] = dr; Ri[i3] = di; }                                             \
} while (0)

__device__ __forceinline__ void gbar(int id) {
    asm volatile("bar.sync %0, %1;" :: "r"(id), "r"(64) : "memory");
}

__device__ __forceinline__ void cpasync16(unsigned saddr, const void* g) {
    asm volatile("cp.async.cg.shared.global [%0], [%1], 16;" :: "r"(saddr), "l"(g) : "memory");
}
#define CP_COMMIT() asm volatile("cp.async.commit_group;" ::: "memory")
#define CP_WAIT0()  asm volatile("cp.async.wait_group 0;" ::: "memory")

// ---------------- radix-2 smem FFT (hilbert only) ----------------
template <bool INV>
__device__ __forceinline__ void fft1024(float2* sm, const float2* tw, int tid) {
#pragma unroll
    for (int e = 0; e < 4; e++) {
        int i = tid + e * NT;
        int j = __brev(i) >> 22;
        if (i < j) { float2 t = sm[i]; sm[i] = sm[j]; sm[j] = t; }
    }
    __syncthreads();
#pragma unroll
    for (int s = 1; s <= 10; s++) {
        int half = 1 << (s - 1);
#pragma unroll
        for (int e = 0; e < 2; e++) {
            int m   = tid + e * NT;
            int pos = m & (half - 1);
            int i0  = ((m >> (s - 1)) << s) + pos;
            int i1  = i0 + half;
            float2 w = tw[pos << (10 - s)];
            float wy = INV ? -w.y : w.y;
            float2 q = sm[i1];
            float2 v = make_float2(q.x * w.x - q.y * wy, q.x * wy + q.y * w.x);
            float2 u = sm[i0];
            sm[i0] = make_float2(u.x + v.x, u.y + v.y);
            sm[i1] = make_float2(u.x - v.x, u.y - v.y);
        }
        __syncthreads();
    }
    if (INV) {
        const float sc = 1.0f / (float)NN;
#pragma unroll
        for (int e = 0; e < 4; e++) { int i = tid + e * NT; sm[i].x *= sc; sm[i].y *= sc; }
        __syncthreads();
    }
}

// ---------------- kernel 1: init ----------------
__global__ void init_kernel() {
    int t = threadIdx.x;
    if (t < BB) {
        g_accS[t] = 0.0; g_accST[t] = 0.0; g_accT[t] = 0.0; g_accT2[t] = 0.0;
        g_accMax[t] = 0u;
    }
    if (t < 512) {
        double ang = -2.0 * 3.14159265358979323846 * (double)t / (double)NN;
        g_tw[t] = make_float2((float)cos(ang), (float)sin(ang));
    }
}

// ---------------- kernel 2: hilbert + modulation ----------------
__global__ void hilbert_kernel(const float* __restrict__ pred) {
    __shared__ float2 sm[NN];
    __shared__ float2 tw[NN / 2];
    int b = blockIdx.x, tid = threadIdx.x;
#pragma unroll
    for (int e = 0; e < 2; e++) tw[tid + e * NT] = g_tw[tid + e * NT];
#pragma unroll
    for (int e = 0; e < 4; e++) {
        int i = tid + e * NT;
        sm[i] = make_float2(pred[b * NN + i], 0.0f);
    }
    __syncthreads();
    fft1024<false>(sm, tw, tid);
#pragma unroll
    for (int e = 0; e < 4; e++) {
        int i = tid + e * NT;
        float h = (i < NN / 2) ? 0.0f : ((i == NN / 2) ? 1.0f : 2.0f);
        sm[i].x *= h; sm[i].y *= h;
    }
    __syncthreads();
    fft1024<true>(sm, tw, tid);
#pragma unroll
    for (int e = 0; e < 4; e++) {
        int i = tid + e * NT;
        float2 a = sm[i];
        g_pa[b * NN + i] = a;
        float ang = (float)(2.0 * 1175000000000000.0 * 1.5e-15 * (double)(i - 512));
        float cs = cosf(ang), sn = sinf(ang);
        g_pam[b * NN + i] = cmulf(a, make_float2(cs, -sn));
    }
}

// ---------------- kernel 3: MSE partials (before shg so shg sits at node 4) ----------------
__global__ void mse_kernel(const float* __restrict__ label) {
    int b = blockIdx.x, tid = threadIdx.x;
    const float* lr = label + (size_t)b * 2 * NN;
    const float* li = lr + NN;

    __shared__ int s_frR, s_laR, s_frI, s_laI;
    if (tid == 0) { s_frR = NN; s_laR = -1; s_frI = NN; s_laI = -1; }
    __syncthreads();
    int frR = NN, laR = -1, frI = NN, laI = -1;
    for (int t = tid; t < NN; t += NT) {
        if (fabsf(lr[t]) > 0.01f) { frR = min(frR, t); laR = max(laR, t); }
        if (fabsf(li[t]) > 0.01f) { frI = min(frI, t); laI = max(laI, t); }
    }
    atomicMin(&s_frR, frR); atomicMax(&s_laR, laR);
    atomicMin(&s_frI, frI); atomicMax(&s_laI, laI);
    __syncthreads();
    int fr_r = (s_frR == NN) ? 0 : s_frR;
    int la_r = (s_laR < 0) ? (NN - 1) : s_laR;
    int fr_i = (s_frI == NN) ? 0 : s_frI;
    int la_i = (s_laI < 0) ? (NN - 1) : s_laI;
    int first = min(fr_r, fr_i);
    int last  = max(la_r, la_i);

    float sR = 0, sI = 0, sInt = 0, sPh = 0;
    for (int t = tid; t < NN; t += NT) {
        float2 p = g_pa[b * NN + t];
        float LR = lr[t], LI = li[t];
        bool inr = (t >= first) && (t < last);
        float pm = inr ? 10.0f : 1.0f;
        float dr = p.x - LR, di = p.y - LI;
        float pint = p.x * p.x + p.y * p.y;
        float lint = LR * LR + LI * LI;
        float dint = pint - lint;
        sR   += dr * dr * pm;
        sI   += di * di * pm;
        sInt += dint * dint * pm;
        if (inr) {
            float dp = atan2f(p.y, p.x) - atan2f(LI, LR);
            sPh += dp * dp;
        }
    }
    float tot = sR + sI + sInt + sPh;
#pragma unroll
    for (int o = 16; o > 0; o >>= 1) tot += __shfl_down_sync(0xffffffffu, tot, o);
    __shared__ float rA[8];
    int w = tid >> 5, lane = tid & 31;
    if (lane == 0) rA[w] = tot;
    __syncthreads();
    if (tid == 0) {
        float a = 0;
#pragma unroll
        for (int i = 0; i < 8; i++) a += rA[i];
        g_mse[b] = a * (1.0f / NN) * 0.25f;   // /MSE_WSUM
    }
}

// ---------------- kernel 4: SHG, packed radix-4 FFT + cp.async tref staging ----------------
#define SWZ(t)  ((t) ^ (((t) >> 4) & 15))

__global__ __launch_bounds__(256, 2) void shg_kernel(const float* __restrict__ tref) {
    extern __shared__ char sraw[];
    float2* paS    = (float2*)sraw;            // 1024  (8KB)
    float2* pamS   = paS + NN;                 // 1024  (8KB)
    float2* twS    = pamS + NN;                // 256   (2KB)
    u64* workAll   = (u64*)(twS + 256);        // 4*1024 u64 (32KB)
    float* trefAll = (float*)(workAll + 4 * NN); // 4*2048 floats (32KB)

    int tid = threadIdx.x;
    int b = blockIdx.y;
    int g = tid >> 6, lt = tid & 63;
    u64* wr = workAll + g * NN;
    float* trefS0 = trefAll + g * 2 * NN;
    float* trefS1 = trefS0 + NN;
    unsigned ts0 = (unsigned)__cvta_generic_to_shared(trefS0);
    unsigned ts1 = (unsigned)__cvta_generic_to_shared(trefS1);

    for (int i = tid; i < NN; i += NT) { paS[i] = g_pa[b * NN + i]; pamS[i] = g_pam[b * NN + i]; }
    if (tid < 256) twS[tid] = g_tw[tid];
    __syncthreads();

    const u64 DT2pk = pk2(2.25e-30f, 2.25e-30f);
    const float* base = tref + (size_t)b * NN * NN;
    int mcoef = lt >> 2, ccoef = lt & 3;
    int kbase = 64 * (lt & 3) + 16 * ((lt >> 2) & 3) + 4 * (lt >> 4);
    int kb2 = kbase >> 2;   // scatter base: addr = 64u + 256v + kb2

    float lmax = 0.0f;
    double dS = 0.0, dST = 0.0, dT = 0.0, dT2a = 0.0;

    u64 Rr[16], Ri[16];

    for (int rr = 0; rr < 2; rr++) {
        int d0 = blockIdx.x * 16 + g * 4 + rr * 2;   // rows d0, d0+1
        int delay0 = d0 - 512;

        // issue async tref staging for both rows (consumed at gather, ~full FFT later)
        {
            const float* r0 = base + (size_t)d0 * NN;
            const float* r1 = r0 + NN;
#pragma unroll
            for (int j = 0; j < 4; j++) {
                cpasync16(ts0 + (unsigned)(j * 1024 + lt * 16), r0 + j * 256 + lt * 4);
                cpasync16(ts1 + (unsigned)(j * 1024 + lt * 16), r1 + j * 256 + lt * 4);
            }
            CP_COMMIT();
        }

        // input build (packed rows d0, d0+1)
#pragma unroll
        for (int e = 0; e < 16; e++) {
            int t = lt + 64 * e;
            float2 pm = pamS[t];
            int t20 = (t - delay0) & (NN - 1);
            float2 p0 = paS[t20];
            float2 p1 = paS[(t20 - 1) & (NN - 1)];
            u64 are = pk2(pm.x, pm.x), aim = pk2(pm.y, pm.y);
            u64 bre = pk2(p0.x, p1.x), bim = pk2(p0.y, p1.y);
            Rr[e] = psub(pmul(are, bre), pmul(aim, bim));
            Ri[e] = pfma(aim, bre, pmul(are, bim));
        }
        // stage 0 (L=1024)
#pragma unroll
        for (int c2 = 0; c2 < 4; c2++) {
            float2 w1 = twS[lt + 64 * c2];
            float2 w2 = cmulf(w1, w1), w3 = cmulf(w1, w2);
            PTw T1 = mkptw(w1), T2 = mkptw(w2), T3 = mkptw(w3);
            PBFLY4(c2, c2 + 4, c2 + 8, c2 + 12, T1, T2, T3);
        }
        // stage 1 (L=256)
        {
            float2 w1 = twS[4 * lt];
            float2 w2 = cmulf(w1, w1), w3 = cmulf(w1, w2);
            PTw T1 = mkptw(w1), T2 = mkptw(w2), T3 = mkptw(w3);
#pragma unroll
            for (int B = 0; B < 4; B++)
                PBFLY4(4 * B, 4 * B + 1, 4 * B + 2, 4 * B + 3, T1, T2, T3);
        }
        // exchange 1, two passes through the single work buffer (re, then im)
#pragma unroll
        for (int e = 0; e < 16; e++) wr[SWZ(lt + 64 * e)] = Rr[e];
        gbar(g + 1);
#pragma unroll
        for (int j = 0; j < 16; j++) Rr[j] = wr[SWZ(64 * mcoef + ccoef + 4 * j)];
        gbar(g + 1);
#pragma unroll
        for (int e = 0; e < 16; e++) wr[SWZ(lt + 64 * e)] = Ri[e];
        gbar(g + 1);
#pragma unroll
        for (int j = 0; j < 16; j++) Ri[j] = wr[SWZ(64 * mcoef + ccoef + 4 * j)];

        // stage 2 (L=64)
#pragma unroll
        for (int j0 = 0; j0 < 4; j0++) {
            float2 w1 = twS[16 * (ccoef + 4 * j0)];
            float2 w2 = cmulf(w1, w1), w3 = cmulf(w1, w2);
            PTw T1 = mkptw(w1), T2 = mkptw(w2), T3 = mkptw(w3);
            PBFLY4(j0, j0 + 4, j0 + 8, j0 + 12, T1, T2, T3);
        }
        // stage 3 (L=16)
        {
            float2 w1 = twS[64 * ccoef];
            float2 w2 = cmulf(w1, w1), w3 = cmulf(w1, w2);
            PTw T1 = mkptw(w1), T2 = mkptw(w2), T3 = mkptw(w3);
#pragma unroll
            for (int h = 0; h < 4; h++)
                PBFLY4(4 * h, 4 * h + 1, 4 * h + 2, 4 * h + 3, T1, T2, T3);
        }
        gbar(g + 1);   // exch1 im reads done before exch2 writes
        // exchange 2, two passes
#pragma unroll
        for (int j = 0; j < 16; j++) wr[SWZ(64 * mcoef + ccoef + 4 * j)] = Rr[j];
        gbar(g + 1);
#pragma unroll
        for (int v = 0; v < 4; v++)
#pragma unroll
            for (int u = 0; u < 4; u++)
                Rr[4 * v + u] = wr[SWZ(4 * lt + 256 * v + u)];
        gbar(g + 1);
#pragma unroll
        for (int j = 0; j < 16; j++) wr[SWZ(64 * mcoef + ccoef + 4 * j)] = Ri[j];
        gbar(g + 1);
#pragma unroll
        for (int v = 0; v < 4; v++)
#pragma unroll
            for (int u = 0; u < 4; u++)
                Ri[4 * v + u] = wr[SWZ(4 * lt + 256 * v + u)];

        // stage 4 (L=4) + magnitude into registers
        u64 rS_pk = pk2(0.f, 0.f);
        u64 spv[16];
#pragma unroll
        for (int v = 0; v < 4; v++) {
            int i0 = 4 * v;
            u64 t0r = padd(Rr[i0], Rr[i0 + 2]), t0i = padd(Ri[i0], Ri[i0 + 2]);
            u64 t1r = psub(Rr[i0], Rr[i0 + 2]), t1i = psub(Ri[i0], Ri[i0 + 2]);
            u64 t2r = padd(Rr[i0 + 1], Rr[i0 + 3]), t2i = padd(Ri[i0 + 1], Ri[i0 + 3]);
            u64 t3r = psub(Rr[i0 + 1], Rr[i0 + 3]), t3i = psub(Ri[i0 + 1], Ri[i0 + 3]);
            u64 yr[4], yi[4];
            yr[0] = padd(t0r, t2r); yi[0] = padd(t0i, t2i);
            yr[1] = padd(t1r, t3i); yi[1] = psub(t1i, t3r);
            yr[2] = psub(t0r, t2r); yi[2] = psub(t0i, t2i);
            yr[3] = psub(t1r, t3i); yi[3] = padd(t1i, t3r);
#pragma unroll
            for (int u = 0; u < 4; u++) {
                u64 sp = pfma(yr[u], yr[u], pmul(yi[u], yi[u]));
                sp = pmul(sp, DT2pk);
                spv[4 * v + u] = sp;
                rS_pk = padd(rS_pk, sp);
                float s0, s1; upk2(sp, s0, s1);
                lmax = fmaxf(lmax, fmaxf(s0, s1));
            }
        }
        gbar(g + 1);   // exch2 im reads done before scatter writes

        // scatter S into wr at addr(k) = (k>>2) + 256*(k&3)
#pragma unroll
        for (int v = 0; v < 4; v++)
#pragma unroll
            for (int u = 0; u < 4; u++)
                wr[64 * u + 256 * v + kb2] = spv[4 * v + u];
        CP_WAIT0();
        gbar(g + 1);

        // gather: conflict-free S LDS + coalesced tref from staged smem
        u64 rST_pk = pk2(0.f, 0.f), rT_pk = pk2(0.f, 0.f), rT2_pk = pk2(0.f, 0.f);
        const float4* t0p = (const float4*)trefS0;
        const float4* t1p = (const float4*)trefS1;
#pragma unroll
        for (int j = 0; j < 4; j++) {
            float4 f0 = t0p[lt + 64 * j];
            float4 f1 = t1p[lt + 64 * j];
            float v0[4] = { f0.x, f0.y, f0.z, f0.w };
            float v1[4] = { f1.x, f1.y, f1.z, f1.w };
            int abase = lt + 64 * (j ^ 2);
#pragma unroll
            for (int q = 0; q < 4; q++) {
                u64 tp = pk2(v0[q], v1[q]);
                u64 sp = wr[abase + 256 * q];
                rT_pk  = padd(rT_pk, tp);
                rT2_pk = pfma(tp, tp, rT2_pk);
                rST_pk = pfma(sp, tp, rST_pk);
            }
        }
        gbar(g + 1);   // wr + trefS reads done before next iter writes

        { float a0, a1;
          upk2(rS_pk, a0, a1);  dS   += (double)a0 + (double)a1;
          upk2(rST_pk, a0, a1); dST  += (double)a0 + (double)a1;
          upk2(rT_pk, a0, a1);  dT   += (double)a0 + (double)a1;
          upk2(rT2_pk, a0, a1); dT2a += (double)a0 + (double)a1; }
    }

    // block reduction
    double vS = dS, vST = dST, vT = dT, vT2 = dT2a; float vM = lmax;
#pragma unroll
    for (int o = 16; o > 0; o >>= 1) {
        vS  += __shfl_down_sync(0xffffffffu, vS,  o);
        vST += __shfl_down_sync(0xffffffffu, vST, o);
        vT  += __shfl_down_sync(0xffffffffu, vT,  o);
        vT2 += __shfl_down_sync(0xffffffffu, vT2, o);
        vM   = fmaxf(vM, __shfl_down_sync(0xffffffffu, vM, o));
    }
    __shared__ double sS[8], sST[8], sT[8], sT2[8];
    __shared__ float  sM[8];
    int w = tid >> 5, lane = tid & 31;
    if (lane == 0) { sS[w] = vS; sST[w] = vST; sT[w] = vT; sT2[w] = vT2; sM[w] = vM; }
    __syncthreads();
    if (tid == 0) {
        double aS = 0, aST = 0, aT = 0, aT2 = 0; float aM = 0.0f;
#pragma unroll
        for (int i = 0; i < 8; i++) {
            aS += sS[i]; aST += sST[i]; aT += sT[i]; aT2 += sT2[i];
            aM = fmaxf(aM, sM[i]);
        }
        atomicAdd(&g_accS[b],  aS);
        atomicAdd(&g_accST[b], aST);
        atomicAdd(&g_accT[b],  aT);
        atomicAdd(&g_accT2[b], aT2);
        atomicMax(&g_accMax[b], __float_as_uint(aM));
    }
}

// ---------------- kernel 5: frog + final mean ----------------
__global__ void finalize_kernel(float* out) {
    int b = threadIdx.x;   // 32 threads
    double M    = (double)__uint_as_float(g_accMax[b]);
    double sum1 = g_accST[b] / M;
    double mu   = sum1 / g_accT2[b];
    double diff = g_accS[b] / M - mu * g_accT[b];
    double r2   = diff * diff;
    float frog  = (r2 == 0.0) ? 0.0f : (float)(sqrt(r2) / (double)NN);
    float v = g_mse[b] + frog;
#pragma unroll
    for (int o = 16; o > 0; o >>= 1) v += __shfl_down_sync(0xffffffffu, v, o);
    if (b == 0) out[0] = v * (1.0f / BB);
}

// ---------------- launch ----------------
extern "C" void kernel_launch(void* const* d_in, const int* in_sizes, int n_in,
                              void* d_out, int out_size) {
    const float* pred  = (const float*)d_in[0];
    const float* label = (const float*)d_in[1];
    const float* shg   = (const float*)d_in[2];
    float* out = (float*)d_out;

    const int SHG_SMEM = (2 * NN + 256) * sizeof(float2)   // paS, pamS, twS
                       + 4 * NN * sizeof(u64)              // work buffers
                       + 4 * 2 * NN * sizeof(float);       // tref staging
    static int attr_done = 0;
    if (!attr_done) {
        cudaFuncSetAttribute(shg_kernel, cudaFuncAttributeMaxDynamicSharedMemorySize, SHG_SMEM);
        attr_done = 1;
    }

    init_kernel<<<1, 512>>>();
    hilbert_kernel<<<BB, NT>>>(pred);
    mse_kernel<<<BB, NT>>>(label);
    shg_kernel<<<dim3(64, BB), NT, SHG_SMEM>>>(shg);   // node 4 -> ncu capture slot
    finalize_kernel<<<1, 32>>>(out);
}

// round 7
// speedup vs baseline: 1.0956x; 1.0956x over previous
#include <cuda_runtime.h>
#include <math.h>

#define NN 1024
#define NT 256
#define BB 32

// ---------------- device scratch ----------------
__device__ float2   g_pa[BB * NN];
__device__ float2   g_pam[BB * NN];
__device__ float2   g_tw[512];            // W_1024^k
__device__ double   g_accS[BB], g_accST[BB], g_accT[BB], g_accT2[BB];
__device__ unsigned g_accMax[BB];
__device__ float    g_mse[BB];

__device__ __forceinline__ float2 cmulf(float2 a, float2 b) {
    return make_float2(a.x * b.x - a.y * b.y, a.x * b.y + a.y * b.x);
}
__device__ __forceinline__ float2 cadd(float2 a, float2 b) { return make_float2(a.x + b.x, a.y + b.y); }
__device__ __forceinline__ float2 csub(float2 a, float2 b) { return make_float2(a.x - b.x, a.y - b.y); }

// radix-4 DIF butterfly
#define BFLY4(A, Bq, C, D, W1, W2, W3) do {                                   \
    float2 t0 = cadd(A, C), t1 = csub(A, C);                                  \
    float2 t2 = cadd(Bq, D), t3 = csub(Bq, D);                                \
    float2 t3m = make_float2(t3.y, -t3.x);  /* -i*t3 */                       \
    A  = cadd(t0, t2);                                                        \
    Bq = cmulf(cadd(t1, t3m), W1);                                            \
    C  = cmulf(csub(t0, t2), W2);                                             \
    D  = cmulf(csub(t1, t3m), W3);                                            \
} while (0)

__device__ __forceinline__ void gbar(int id) {
    asm volatile("bar.sync %0, %1;" :: "r"(id), "r"(64) : "memory");
}

// ---------------- radix-2 smem FFT (hilbert only) ----------------
template <bool INV>
__device__ __forceinline__ void fft1024(float2* sm, const float2* tw, int tid) {
#pragma unroll
    for (int e = 0; e < 4; e++) {
        int i = tid + e * NT;
        int j = __brev(i) >> 22;
        if (i < j) { float2 t = sm[i]; sm[i] = sm[j]; sm[j] = t; }
    }
    __syncthreads();
#pragma unroll
    for (int s = 1; s <= 10; s++) {
        int half = 1 << (s - 1);
#pragma unroll
        for (int e = 0; e < 2; e++) {
            int m   = tid + e * NT;
            int pos = m & (half - 1);
            int i0  = ((m >> (s - 1)) << s) + pos;
            int i1  = i0 + half;
            float2 w = tw[pos << (10 - s)];
            float wy = INV ? -w.y : w.y;
            float2 q = sm[i1];
            float2 v = make_float2(q.x * w.x - q.y * wy, q.x * wy + q.y * w.x);
            float2 u = sm[i0];
            sm[i0] = make_float2(u.x + v.x, u.y + v.y);
            sm[i1] = make_float2(u.x - v.x, u.y - v.y);
        }
        __syncthreads();
    }
    if (INV) {
        const float sc = 1.0f / (float)NN;
#pragma unroll
        for (int e = 0; e < 4; e++) { int i = tid + e * NT; sm[i].x *= sc; sm[i].y *= sc; }
        __syncthreads();
    }
}

// ---------------- kernel 1: init ----------------
__global__ void init_kernel() {
    int t = threadIdx.x;
    if (t < BB) {
        g_accS[t] = 0.0; g_accST[t] = 0.0; g_accT[t] = 0.0; g_accT2[t] = 0.0;
        g_accMax[t] = 0u;
    }
    if (t < 512) {
        double ang = -2.0 * 3.14159265358979323846 * (double)t / (double)NN;
        g_tw[t] = make_float2((float)cos(ang), (float)sin(ang));
    }
}

// ---------------- kernel 2: hilbert + modulation ----------------
__global__ void hilbert_kernel(const float* __restrict__ pred) {
    __shared__ float2 sm[NN];
    __shared__ float2 tw[NN / 2];
    int b = blockIdx.x, tid = threadIdx.x;
#pragma unroll
    for (int e = 0; e < 2; e++) tw[tid + e * NT] = g_tw[tid + e * NT];
#pragma unroll
    for (int e = 0; e < 4; e++) {
        int i = tid + e * NT;
        sm[i] = make_float2(pred[b * NN + i], 0.0f);
    }
    __syncthreads();
    fft1024<false>(sm, tw, tid);
#pragma unroll
    for (int e = 0; e < 4; e++) {
        int i = tid + e * NT;
        float h = (i < NN / 2) ? 0.0f : ((i == NN / 2) ? 1.0f : 2.0f);
        sm[i].x *= h; sm[i].y *= h;
    }
    __syncthreads();
    fft1024<true>(sm, tw, tid);
#pragma unroll
    for (int e = 0; e < 4; e++) {
        int i = tid + e * NT;
        float2 a = sm[i];
        g_pa[b * NN + i] = a;
        float ang = (float)(2.0 * 1175000000000000.0 * 1.5e-15 * (double)(i - 512));
        float cs = cosf(ang), sn = sinf(ang);
        g_pam[b * NN + i] = cmulf(a, make_float2(cs, -sn));
    }
}

// ---------------- kernel 3: MSE partials ----------------
__global__ void mse_kernel(const float* __restrict__ label) {
    int b = blockIdx.x, tid = threadIdx.x;
    const float* lr = label + (size_t)b * 2 * NN;
    const float* li = lr + NN;

    __shared__ int s_frR, s_laR, s_frI, s_laI;
    if (tid == 0) { s_frR = NN; s_laR = -1; s_frI = NN; s_laI = -1; }
    __syncthreads();
    int frR = NN, laR = -1, frI = NN, laI = -1;
    for (int t = tid; t < NN; t += NT) {
        if (fabsf(lr[t]) > 0.01f) { frR = min(frR, t); laR = max(laR, t); }
        if (fabsf(li[t]) > 0.01f) { frI = min(frI, t); laI = max(laI, t); }
    }
    atomicMin(&s_frR, frR); atomicMax(&s_laR, laR);
    atomicMin(&s_frI, frI); atomicMax(&s_laI, laI);
    __syncthreads();
    int fr_r = (s_frR == NN) ? 0 : s_frR;
    int la_r = (s_laR < 0) ? (NN - 1) : s_laR;
    int fr_i = (s_frI == NN) ? 0 : s_frI;
    int la_i = (s_laI < 0) ? (NN - 1) : s_laI;
    int first = min(fr_r, fr_i);
    int last  = max(la_r, la_i);

    float sR = 0, sI = 0, sInt = 0, sPh = 0;
    for (int t = tid; t < NN; t += NT) {
        float2 p = g_pa[b * NN + t];
        float LR = lr[t], LI = li[t];
        bool inr = (t >= first) && (t < last);
        float pm = inr ? 10.0f : 1.0f;
        float dr = p.x - LR, di = p.y - LI;
        float pint = p.x * p.x + p.y * p.y;
        float lint = LR * LR + LI * LI;
        float dint = pint - lint;
        sR   += dr * dr * pm;
        sI   += di * di * pm;
        sInt += dint * dint * pm;
        if (inr) {
            float dp = atan2f(p.y, p.x) - atan2f(LI, LR);
            sPh += dp * dp;
        }
    }
    float tot = sR + sI + sInt + sPh;
#pragma unroll
    for (int o = 16; o > 0; o >>= 1) tot += __shfl_down_sync(0xffffffffu, tot, o);
    __shared__ float rA[8];
    int w = tid >> 5, lane = tid & 31;
    if (lane == 0) rA[w] = tot;
    __syncthreads();
    if (tid == 0) {
        float a = 0;
#pragma unroll
        for (int i = 0; i < 8; i++) a += rA[i];
        g_mse[b] = a * (1.0f / NN) * 0.25f;
    }
}

// ---------------- kernel 4: SHG, scalar radix-4, 3 blocks/SM ----------------
#define SWZ(t) ((t) ^ (((t) >> 4) & 15))

__global__ __launch_bounds__(256, 3) void shg_kernel(const float* __restrict__ tref) {
    extern __shared__ char sraw[];
    float2* paS     = (float2*)sraw;            // 1024 (8KB)
    float2* pamS    = paS + NN;                 // 1024 (8KB)
    float2* twS     = pamS + NN;                // 256  (2KB)
    float2* workAll = twS + 256;                // 4*1024 (32KB)

    int tid = threadIdx.x;
    int b = blockIdx.y;
    int g = tid >> 6, lt = tid & 63;
    float2* work = workAll + g * NN;

    for (int i = tid; i < NN; i += NT) { paS[i] = g_pa[b * NN + i]; pamS[i] = g_pam[b * NN + i]; }
    if (tid < 256) twS[tid] = g_tw[tid];
    __syncthreads();

    const float DT2 = 2.25e-30f;
    const float* base = tref + (size_t)b * NN * NN;
    int mcoef = lt >> 2, ccoef = lt & 3;
    int kbase = 64 * (lt & 3) + 16 * ((lt >> 2) & 3) + 4 * (lt >> 4);
    int kq = kbase >> 2;   // float4 index base within a row

    float lmax = 0.0f;
    double dS = 0.0, dST = 0.0, dT = 0.0, dT2a = 0.0;

    for (int rr = 0; rr < 4; rr++) {
        int d = blockIdx.x * 16 + g * 4 + rr;   // 0..1023
        int delay = d - 512;

        // input build, layout A: r[e] = c[lt + 64e]
        float2 r[16];
#pragma unroll
        for (int e = 0; e < 16; e++) {
            int t  = lt + 64 * e;
            int t2 = (t - delay) & (NN - 1);
            r[e] = cmulf(pamS[t], paS[t2]);
        }
        // stage 0 (L=1024)
#pragma unroll
        for (int c2 = 0; c2 < 4; c2++) {
            float2 w1 = twS[lt + 64 * c2];
            float2 w2 = cmulf(w1, w1), w3 = cmulf(w1, w2);
            BFLY4(r[c2], r[c2 + 4], r[c2 + 8], r[c2 + 12], w1, w2, w3);
        }
        // stage 1 (L=256)
        {
            float2 w1 = twS[4 * lt];
            float2 w2 = cmulf(w1, w1), w3 = cmulf(w1, w2);
#pragma unroll
            for (int B = 0; B < 4; B++)
                BFLY4(r[4 * B], r[4 * B + 1], r[4 * B + 2], r[4 * B + 3], w1, w2, w3);
        }
        // exchange 1: layout A -> layout B
#pragma unroll
        for (int e = 0; e < 16; e++) { int t = lt + 64 * e; work[SWZ(t)] = r[e]; }
        gbar(g + 1);
#pragma unroll
        for (int j = 0; j < 16; j++) { int t = 64 * mcoef + ccoef + 4 * j; r[j] = work[SWZ(t)]; }
        // stage 2 (L=64)
#pragma unroll
        for (int j0 = 0; j0 < 4; j0++) {
            float2 w1 = twS[16 * (ccoef + 4 * j0)];
            float2 w2 = cmulf(w1, w1), w3 = cmulf(w1, w2);
            BFLY4(r[j0], r[j0 + 4], r[j0 + 8], r[j0 + 12], w1, w2, w3);
        }
        // stage 3 (L=16)
        {
            float2 w1 = twS[64 * ccoef];
            float2 w2 = cmulf(w1, w1), w3 = cmulf(w1, w2);
#pragma unroll
            for (int h = 0; h < 4; h++)
                BFLY4(r[4 * h], r[4 * h + 1], r[4 * h + 2], r[4 * h + 3], w1, w2, w3);
        }
        gbar(g + 1);   // exch1 reads done before overwrite
        // exchange 2: layout B -> layout C (writes)
#pragma unroll
        for (int j = 0; j < 16; j++) {
            int t = 64 * mcoef + ccoef + 4 * j;
            work[SWZ(t)] = r[j];
        }
        // issue tref LDG.128s now; consumed after exch2 reads + stage 4 (latency cover)
        const float4* rowp = (const float4*)(base + (size_t)d * NN);
        float4 f4[4];
#pragma unroll
        for (int j = 0; j < 4; j++) f4[j] = rowp[64 * j + kq];

        gbar(g + 1);
#pragma unroll
        for (int v = 0; v < 4; v++)
#pragma unroll
            for (int u = 0; u < 4; u++) {
                int t = 4 * lt + 256 * v + u;
                r[4 * v + u] = work[SWZ(t)];
            }
        gbar(g + 1);   // exch2 reads done -> next iter may write

        // rT / rT2 from the same tref values (bijection covers the row once)
        float rT = 0.0f, rT2 = 0.0f;
#pragma unroll
        for (int j = 0; j < 4; j++) {
            rT  += f4[j].x + f4[j].y + f4[j].z + f4[j].w;
            rT2 += f4[j].x * f4[j].x + f4[j].y * f4[j].y
                 + f4[j].z * f4[j].z + f4[j].w * f4[j].w;
        }

        // stage 4 (L=4) + magnitude + fused reductions
        // bin k = 256u + kbase + v  ->  col = k ^ 512 -> f4[u^2], component v
        float rS = 0.0f, rST = 0.0f;
#pragma unroll
        for (int v = 0; v < 4; v++) {
            float2 a = r[4 * v], bq = r[4 * v + 1], cq = r[4 * v + 2], dq = r[4 * v + 3];
            float2 t0 = cadd(a, cq), t1 = csub(a, cq);
            float2 t2 = cadd(bq, dq), t3 = csub(bq, dq);
            float2 t3m = make_float2(t3.y, -t3.x);
            float2 y0 = cadd(t0, t2);
            float2 y1 = cadd(t1, t3m);
            float2 y2 = csub(t0, t2);
            float2 y3 = csub(t1, t3m);
            float s0 = (y0.x * y0.x + y0.y * y0.y) * DT2;
            float s1 = (y1.x * y1.x + y1.y * y1.y) * DT2;
            float s2 = (y2.x * y2.x + y2.y * y2.y) * DT2;
            float s3 = (y3.x * y3.x + y3.y * y3.y) * DT2;
            lmax = fmaxf(lmax, fmaxf(fmaxf(s0, s1), fmaxf(s2, s3)));
            rS += s0 + s1 + s2 + s3;
            const float t0v = (v == 0) ? f4[2].x : (v == 1) ? f4[2].y : (v == 2) ? f4[2].z : f4[2].w;
            const float t1v = (v == 0) ? f4[3].x : (v == 1) ? f4[3].y : (v == 2) ? f4[3].z : f4[3].w;
            const float t2v = (v == 0) ? f4[0].x : (v == 1) ? f4[0].y : (v == 2) ? f4[0].z : f4[0].w;
            const float t3v = (v == 0) ? f4[1].x : (v == 1) ? f4[1].y : (v == 2) ? f4[1].z : f4[1].w;
            rST += s0 * t0v + s1 * t1v + s2 * t2v + s3 * t3v;
        }
        dS += rS; dST += rST; dT += rT; dT2a += rT2;
    }

    // block reduction
    double vS = dS, vST = dST, vT = dT, vT2 = dT2a; float vM = lmax;
#pragma unroll
    for (int o = 16; o > 0; o >>= 1) {
        vS  += __shfl_down_sync(0xffffffffu, vS,  o);
        vST += __shfl_down_sync(0xffffffffu, vST, o);
        vT  += __shfl_down_sync(0xffffffffu, vT,  o);
        vT2 += __shfl_down_sync(0xffffffffu, vT2, o);
        vM   = fmaxf(vM, __shfl_down_sync(0xffffffffu, vM, o));
    }
    __shared__ double sS[8], sST[8], sT[8], sT2[8];
    __shared__ float  sM[8];
    int w = tid >> 5, lane = tid & 31;
    if (lane == 0) { sS[w] = vS; sST[w] = vST; sT[w] = vT; sT2[w] = vT2; sM[w] = vM; }
    __syncthreads();
    if (tid == 0) {
        double aS = 0, aST = 0, aT = 0, aT2 = 0; float aM = 0.0f;
#pragma unroll
        for (int i = 0; i < 8; i++) {
            aS += sS[i]; aST += sST[i]; aT += sT[i]; aT2 += sT2[i];
            aM = fmaxf(aM, sM[i]);
        }
        atomicAdd(&g_accS[b],  aS);
        atomicAdd(&g_accST[b], aST);
        atomicAdd(&g_accT[b],  aT);
        atomicAdd(&g_accT2[b], aT2);
        atomicMax(&g_accMax[b], __float_as_uint(aM));
    }
}

// ---------------- kernel 5: frog + final mean ----------------
__global__ void finalize_kernel(float* out) {
    int b = threadIdx.x;   // 32 threads
    double M    = (double)__uint_as_float(g_accMax[b]);
    double sum1 = g_accST[b] / M;
    double mu   = sum1 / g_accT2[b];
    double diff = g_accS[b] / M - mu * g_accT[b];
    double r2   = diff * diff;
    float frog  = (r2 == 0.0) ? 0.0f : (float)(sqrt(r2) / (double)NN);
    float v = g_mse[b] + frog;
#pragma unroll
    for (int o = 16; o > 0; o >>= 1) v += __shfl_down_sync(0xffffffffu, v, o);
    if (b == 0) out[0] = v * (1.0f / BB);
}

// ---------------- launch ----------------
extern "C" void kernel_launch(void* const* d_in, const int* in_sizes, int n_in,
                              void* d_out, int out_size) {
    const float* pred  = (const float*)d_in[0];
    const float* label = (const float*)d_in[1];
    const float* shg   = (const float*)d_in[2];
    float* out = (float*)d_out;

    const int SHG_SMEM = (2 * NN + 256 + 4 * NN) * sizeof(float2);  // 50KB
    static int attr_done = 0;
    if (!attr_done) {
        cudaFuncSetAttribute(shg_kernel, cudaFuncAttributeMaxDynamicSharedMemorySize, SHG_SMEM);
        attr_done = 1;
    }

    init_kernel<<<1, 512>>>();
    hilbert_kernel<<<BB, NT>>>(pred);
    mse_kernel<<<BB, NT>>>(label);
    shg_kernel<<<dim3(64, BB), NT, SHG_SMEM>>>(shg);   // node 4 -> ncu capture slot
    finalize_kernel<<<1, 32>>>(out);
}

// round 8
// speedup vs baseline: 1.1723x; 1.0700x over previous
#include <cuda_runtime.h>
#include <math.h>

#define NN 1024
#define NT 256
#define BB 32

// ---------------- device scratch ----------------
__device__ float2   g_pa[BB * NN];
__device__ float2   g_pam[BB * NN];
__device__ float2   g_tw[512];            // W_1024^k
__device__ double   g_accS[BB], g_accST[BB], g_accT[BB], g_accT2[BB];
__device__ unsigned g_accMax[BB];
__device__ float    g_mse[BB];

__device__ __forceinline__ float2 cmulf(float2 a, float2 b) {
    return make_float2(a.x * b.x - a.y * b.y, a.x * b.y + a.y * b.x);
}
__device__ __forceinline__ float2 cadd(float2 a, float2 b) { return make_float2(a.x + b.x, a.y + b.y); }
__device__ __forceinline__ float2 csub(float2 a, float2 b) { return make_float2(a.x - b.x, a.y - b.y); }

// radix-4 DIF butterfly
#define BFLY4(A, Bq, C, D, W1, W2, W3) do {                                   \
    float2 t0 = cadd(A, C), t1 = csub(A, C);                                  \
    float2 t2 = cadd(Bq, D), t3 = csub(Bq, D);                                \
    float2 t3m = make_float2(t3.y, -t3.x);  /* -i*t3 */                       \
    A  = cadd(t0, t2);                                                        \
    Bq = cmulf(cadd(t1, t3m), W1);                                            \
    C  = cmulf(csub(t0, t2), W2);                                             \
    D  = cmulf(csub(t1, t3m), W3);                                            \
} while (0)

__device__ __forceinline__ void gbar(int id) {
    asm volatile("bar.sync %0, %1;" :: "r"(id), "r"(64) : "memory");
}

// ---------------- radix-2 smem FFT (hilbert only) ----------------
template <bool INV>
__device__ __forceinline__ void fft1024(float2* sm, const float2* tw, int tid) {
#pragma unroll
    for (int e = 0; e < 4; e++) {
        int i = tid + e * NT;
        int j = __brev(i) >> 22;
        if (i < j) { float2 t = sm[i]; sm[i] = sm[j]; sm[j] = t; }
    }
    __syncthreads();
#pragma unroll
    for (int s = 1; s <= 10; s++) {
        int half = 1 << (s - 1);
#pragma unroll
        for (int e = 0; e < 2; e++) {
            int m   = tid + e * NT;
            int pos = m & (half - 1);
            int i0  = ((m >> (s - 1)) << s) + pos;
            int i1  = i0 + half;
            float2 w = tw[pos << (10 - s)];
            float wy = INV ? -w.y : w.y;
            float2 q = sm[i1];
            float2 v = make_float2(q.x * w.x - q.y * wy, q.x * wy + q.y * w.x);
            float2 u = sm[i0];
            sm[i0] = make_float2(u.x + v.x, u.y + v.y);
            sm[i1] = make_float2(u.x - v.x, u.y - v.y);
        }
        __syncthreads();
    }
    if (INV) {
        const float sc = 1.0f / (float)NN;
#pragma unroll
        for (int e = 0; e < 4; e++) { int i = tid + e * NT; sm[i].x *= sc; sm[i].y *= sc; }
        __syncthreads();
    }
}

// ---------------- kernel 1: init ----------------
__global__ void init_kernel() {
    int t = threadIdx.x;
    if (t < BB) {
        g_accS[t] = 0.0; g_accST[t] = 0.0; g_accT[t] = 0.0; g_accT2[t] = 0.0;
        g_accMax[t] = 0u;
    }
    if (t < 512) {
        double ang = -2.0 * 3.14159265358979323846 * (double)t / (double)NN;
        g_tw[t] = make_float2((float)cos(ang), (float)sin(ang));
    }
}

// ---------------- kernel 2: hilbert + modulation ----------------
__global__ void hilbert_kernel(const float* __restrict__ pred) {
    __shared__ float2 sm[NN];
    __shared__ float2 tw[NN / 2];
    int b = blockIdx.x, tid = threadIdx.x;
#pragma unroll
    for (int e = 0; e < 2; e++) tw[tid + e * NT] = g_tw[tid + e * NT];
#pragma unroll
    for (int e = 0; e < 4; e++) {
        int i = tid + e * NT;
        sm[i] = make_float2(pred[b * NN + i], 0.0f);
    }
    __syncthreads();
    fft1024<false>(sm, tw, tid);
#pragma unroll
    for (int e = 0; e < 4; e++) {
        int i = tid + e * NT;
        float h = (i < NN / 2) ? 0.0f : ((i == NN / 2) ? 1.0f : 2.0f);
        sm[i].x *= h; sm[i].y *= h;
    }
    __syncthreads();
    fft1024<true>(sm, tw, tid);
#pragma unroll
    for (int e = 0; e < 4; e++) {
        int i = tid + e * NT;
        float2 a = sm[i];
        g_pa[b * NN + i] = a;
        float ang = (float)(2.0 * 1175000000000000.0 * 1.5e-15 * (double)(i - 512));
        float cs = cosf(ang), sn = sinf(ang);
        g_pam[b * NN + i] = cmulf(a, make_float2(cs, -sn));
    }
}

// ---------------- kernel 3: MSE partials ----------------
__global__ void mse_kernel(const float* __restrict__ label) {
    int b = blockIdx.x, tid = threadIdx.x;
    const float* lr = label + (size_t)b * 2 * NN;
    const float* li = lr + NN;

    __shared__ int s_frR, s_laR, s_frI, s_laI;
    if (tid == 0) { s_frR = NN; s_laR = -1; s_frI = NN; s_laI = -1; }
    __syncthreads();
    int frR = NN, laR = -1, frI = NN, laI = -1;
    for (int t = tid; t < NN; t += NT) {
        if (fabsf(lr[t]) > 0.01f) { frR = min(frR, t); laR = max(laR, t); }
        if (fabsf(li[t]) > 0.01f) { frI = min(frI, t); laI = max(laI, t); }
    }
    atomicMin(&s_frR, frR); atomicMax(&s_laR, laR);
    atomicMin(&s_frI, frI); atomicMax(&s_laI, laI);
    __syncthreads();
    int fr_r = (s_frR == NN) ? 0 : s_frR;
    int la_r = (s_laR < 0) ? (NN - 1) : s_laR;
    int fr_i = (s_frI == NN) ? 0 : s_frI;
    int la_i = (s_laI < 0) ? (NN - 1) : s_laI;
    int first = min(fr_r, fr_i);
    int last  = max(la_r, la_i);

    float sR = 0, sI = 0, sInt = 0, sPh = 0;
    for (int t = tid; t < NN; t += NT) {
        float2 p = g_pa[b * NN + t];
        float LR = lr[t], LI = li[t];
        bool inr = (t >= first) && (t < last);
        float pm = inr ? 10.0f : 1.0f;
        float dr = p.x - LR, di = p.y - LI;
        float pint = p.x * p.x + p.y * p.y;
        float lint = LR * LR + LI * LI;
        float dint = pint - lint;
        sR   += dr * dr * pm;
        sI   += di * di * pm;
        sInt += dint * dint * pm;
        if (inr) {
            float dp = atan2f(p.y, p.x) - atan2f(LI, LR);
            sPh += dp * dp;
        }
    }
    float tot = sR + sI + sInt + sPh;
#pragma unroll
    for (int o = 16; o > 0; o >>= 1) tot += __shfl_down_sync(0xffffffffu, tot, o);
    __shared__ float rA[8];
    int w = tid >> 5, lane = tid & 31;
    if (lane == 0) rA[w] = tot;
    __syncthreads();
    if (tid == 0) {
        float a = 0;
#pragma unroll
        for (int i = 0; i < 8; i++) a += rA[i];
        g_mse[b] = a * (1.0f / NN) * 0.25f;
    }
}

// ---------------- kernel 4: SHG, scalar radix-4, padded-affine exchanges ----------------
// padded address: addr(t) = t + (t>>4); buffer = 1088 elements per group.
#define WPAD 1088

__global__ __launch_bounds__(256, 3) void shg_kernel(const float* __restrict__ tref) {
    extern __shared__ char sraw[];
    float2* paS2    = (float2*)sraw;            // 2048 (16KB, pa duplicated)
    float2* pamS    = paS2 + 2 * NN;            // 1024 (8KB)
    float2* twS     = pamS + NN;                // 256  (2KB)
    float2* workAll = twS + 256;                // 4*1088 (34KB)

    int tid = threadIdx.x;
    int b = blockIdx.y;
    int g = tid >> 6, lt = tid & 63;
    float2* work = workAll + g * WPAD;

    for (int i = tid; i < NN; i += NT) {
        float2 v = g_pa[b * NN + i];
        paS2[i] = v; paS2[i + NN] = v;
        pamS[i] = g_pam[b * NN + i];
    }
    if (tid < 256) twS[tid] = g_tw[tid];
    __syncthreads();

    const float DT2 = 2.25e-30f;
    const float* base = tref + (size_t)b * NN * NN;
    int mcoef = lt >> 2, ccoef = lt & 3;
    int kbase = 64 * (lt & 3) + 16 * ((lt >> 2) & 3) + 4 * (lt >> 4);
    int kq = kbase >> 2;   // float4 index base within a tref row

    // loop-invariant padded-affine bases (all per-access offsets are immediates)
    const int w1b = lt + (lt >> 4);          // exch1 write: + 68e
    const int r1b = 68 * mcoef + ccoef;      // exch1 read / exch2 write: + 4j + (j>>2)
    const int r2b = 4 * lt + (lt >> 2);      // exch2 read: + 272v + u

    float lmax = 0.0f;
    double dS = 0.0, dST = 0.0, dT = 0.0, dT2a = 0.0;

    for (int rr = 0; rr < 4; rr++) {
        int d = blockIdx.x * 16 + g * 4 + rr;   // 0..1023
        int delay = d - 512;
        int tb = (lt - delay) & (NN - 1);       // per-row base into doubled paS2

        // input build, layout A: r[e] = pam[lt+64e] * pa[(lt+64e-delay) mod N]
        float2 r[16];
#pragma unroll
        for (int e = 0; e < 16; e++)
            r[e] = cmulf(pamS[lt + 64 * e], paS2[tb + 64 * e]);

        // stage 0 (L=1024)
#pragma unroll
        for (int c2 = 0; c2 < 4; c2++) {
            float2 w1 = twS[lt + 64 * c2];
            float2 w2 = cmulf(w1, w1), w3 = cmulf(w1, w2);
            BFLY4(r[c2], r[c2 + 4], r[c2 + 8], r[c2 + 12], w1, w2, w3);
        }
        // stage 1 (L=256)
        {
            float2 w1 = twS[4 * lt];
            float2 w2 = cmulf(w1, w1), w3 = cmulf(w1, w2);
#pragma unroll
            for (int B = 0; B < 4; B++)
                BFLY4(r[4 * B], r[4 * B + 1], r[4 * B + 2], r[4 * B + 3], w1, w2, w3);
        }
        // exchange 1: layout A -> layout B
#pragma unroll
        for (int e = 0; e < 16; e++) work[w1b + 68 * e] = r[e];
        gbar(g + 1);
#pragma unroll
        for (int j = 0; j < 16; j++) r[j] = work[r1b + 4 * j + (j >> 2)];
        // stage 2 (L=64)
#pragma unroll
        for (int j0 = 0; j0 < 4; j0++) {
            float2 w1 = twS[16 * (ccoef + 4 * j0)];
            float2 w2 = cmulf(w1, w1), w3 = cmulf(w1, w2);
            BFLY4(r[j0], r[j0 + 4], r[j0 + 8], r[j0 + 12], w1, w2, w3);
        }
        // stage 3 (L=16)
        {
            float2 w1 = twS[64 * ccoef];
            float2 w2 = cmulf(w1, w1), w3 = cmulf(w1, w2);
#pragma unroll
            for (int h = 0; h < 4; h++)
                BFLY4(r[4 * h], r[4 * h + 1], r[4 * h + 2], r[4 * h + 3], w1, w2, w3);
        }
        gbar(g + 1);   // exch1 reads done before overwrite
        // exchange 2 writes: layout B positions
#pragma unroll
        for (int j = 0; j < 16; j++) work[r1b + 4 * j + (j >> 2)] = r[j];

        // issue tref LDG.128s now; consumed after exch2 reads + stage 4 (latency cover)
        const float4* rowp = (const float4*)(base + (size_t)d * NN);
        float4 f4[4];
#pragma unroll
        for (int j = 0; j < 4; j++) f4[j] = rowp[64 * j + kq];

        gbar(g + 1);
#pragma unroll
        for (int v = 0; v < 4; v++)
#pragma unroll
            for (int u = 0; u < 4; u++)
                r[4 * v + u] = work[r2b + 272 * v + u];
        gbar(g + 1);   // exch2 reads done -> next iter may write

        // rT / rT2 from the same tref values (bijection covers the row once)
        float rT = 0.0f, rT2 = 0.0f;
#pragma unroll
        for (int j = 0; j < 4; j++) {
            rT  += f4[j].x + f4[j].y + f4[j].z + f4[j].w;
            rT2 += f4[j].x * f4[j].x + f4[j].y * f4[j].y
                 + f4[j].z * f4[j].z + f4[j].w * f4[j].w;
        }

        // stage 4 (L=4) + magnitude + fused reductions
        // bin k = 256u + kbase + v  ->  col = k ^ 512 -> f4[u^2], component v
        float rS = 0.0f, rST = 0.0f;
#pragma unroll
        for (int v = 0; v < 4; v++) {
            float2 a = r[4 * v], bq = r[4 * v + 1], cq = r[4 * v + 2], dq = r[4 * v + 3];
            float2 t0 = cadd(a, cq), t1 = csub(a, cq);
            float2 t2 = cadd(bq, dq), t3 = csub(bq, dq);
            float2 t3m = make_float2(t3.y, -t3.x);
            float2 y0 = cadd(t0, t2);
            float2 y1 = cadd(t1, t3m);
            float2 y2 = csub(t0, t2);
            float2 y3 = csub(t1, t3m);
            float s0 = (y0.x * y0.x + y0.y * y0.y) * DT2;
            float s1 = (y1.x * y1.x + y1.y * y1.y) * DT2;
            float s2 = (y2.x * y2.x + y2.y * y2.y) * DT2;
            float s3 = (y3.x * y3.x + y3.y * y3.y) * DT2;
            lmax = fmaxf(lmax, fmaxf(fmaxf(s0, s1), fmaxf(s2, s3)));
            rS += s0 + s1 + s2 + s3;
            const float t0v = (v == 0) ? f4[2].x : (v == 1) ? f4[2].y : (v == 2) ? f4[2].z : f4[2].w;
            const float t1v = (v == 0) ? f4[3].x : (v == 1) ? f4[3].y : (v == 2) ? f4[3].z : f4[3].w;
            const float t2v = (v == 0) ? f4[0].x : (v == 1) ? f4[0].y : (v == 2) ? f4[0].z : f4[0].w;
            const float t3v = (v == 0) ? f4[1].x : (v == 1) ? f4[1].y : (v == 2) ? f4[1].z : f4[1].w;
            rST += s0 * t0v + s1 * t1v + s2 * t2v + s3 * t3v;
        }
        dS += rS; dST += rST; dT += rT; dT2a += rT2;
    }

    // block reduction
    double vS = dS, vST = dST, vT = dT, vT2 = dT2a; float vM = lmax;
#pragma unroll
    for (int o = 16; o > 0; o >>= 1) {
        vS  += __shfl_down_sync(0xffffffffu, vS,  o);
        vST += __shfl_down_sync(0xffffffffu, vST, o);
        vT  += __shfl_down_sync(0xffffffffu, vT,  o);
        vT2 += __shfl_down_sync(0xffffffffu, vT2, o);
        vM   = fmaxf(vM, __shfl_down_sync(0xffffffffu, vM, o));
    }
    __shared__ double sS[8], sST[8], sT[8], sT2[8];
    __shared__ float  sM[8];
    int w = tid >> 5, lane = tid & 31;
    if (lane == 0) { sS[w] = vS; sST[w] = vST; sT[w] = vT; sT2[w] = vT2; sM[w] = vM; }
    __syncthreads();
    if (tid == 0) {
        double aS = 0, aST = 0, aT = 0, aT2 = 0; float aM = 0.0f;
#pragma unroll
        for (int i = 0; i < 8; i++) {
            aS += sS[i]; aST += sST[i]; aT += sT[i]; aT2 += sT2[i];
            aM = fmaxf(aM, sM[i]);
        }
        atomicAdd(&g_accS[b],  aS);
        atomicAdd(&g_accST[b], aST);
        atomicAdd(&g_accT[b],  aT);
        atomicAdd(&g_accT2[b], aT2);
        atomicMax(&g_accMax[b], __float_as_uint(aM));
    }
}

// ---------------- kernel 5: frog + final mean ----------------
__global__ void finalize_kernel(float* out) {
    int b = threadIdx.x;   // 32 threads
    double M    = (double)__uint_as_float(g_accMax[b]);
    double sum1 = g_accST[b] / M;
    double mu   = sum1 / g_accT2[b];
    double diff = g_accS[b] / M - mu * g_accT[b];
    double r2   = diff * diff;
    float frog  = (r2 == 0.0) ? 0.0f : (float)(sqrt(r2) / (double)NN);
    float v = g_mse[b] + frog;
#pragma unroll
    for (int o = 16; o > 0; o >>= 1) v += __shfl_down_sync(0xffffffffu, v, o);
    if (b == 0) out[0] = v * (1.0f / BB);
}

// ---------------- launch ----------------
extern "C" void kernel_launch(void* const* d_in, const int* in_sizes, int n_in,
                              void* d_out, int out_size) {
    const float* pred  = (const float*)d_in[0];
    const float* label = (const float*)d_in[1];
    const float* shg   = (const float*)d_in[2];
    float* out = (float*)d_out;

    const int SHG_SMEM = (2 * NN + NN + 256 + 4 * WPAD) * sizeof(float2);  // 60KB
    static int attr_done = 0;
    if (!attr_done) {
        cudaFuncSetAttribute(shg_kernel, cudaFuncAttributeMaxDynamicSharedMemorySize, SHG_SMEM);
        attr_done = 1;
    }

    init_kernel<<<1, 512>>>();
    hilbert_kernel<<<BB, NT>>>(pred);
    mse_kernel<<<BB, NT>>>(label);
    shg_kernel<<<dim3(64, BB), NT, SHG_SMEM>>>(shg);   // node 4 -> ncu capture slot
    finalize_kernel<<<1, 32>>>(out);
}

// round 10
// speedup vs baseline: 1.3824x; 1.1793x over previous
#include <cuda_runtime.h>
#include <math.h>

#define NN 1024
#define NT 256
#define BB 32

// ---------------- device scratch ----------------
__device__ float2   g_pa[BB * NN];
__device__ float2   g_pam[BB * NN];
__device__ float2   g_tw[512];            // W_1024^k
__device__ double   g_accS[BB], g_accST[BB], g_accT[BB], g_accT2[BB];
__device__ unsigned g_accMax[BB];
__device__ float    g_mse[BB];

__device__ __forceinline__ float2 cmulf(float2 a, float2 b) {
    return make_float2(a.x * b.x - a.y * b.y, a.x * b.y + a.y * b.x);
}
__device__ __forceinline__ float2 cadd(float2 a, float2 b) { return make_float2(a.x + b.x, a.y + b.y); }
__device__ __forceinline__ float2 csub(float2 a, float2 b) { return make_float2(a.x - b.x, a.y - b.y); }

// radix-4 DIF butterfly
#define BFLY4(A, Bq, C, D, W1, W2, W3) do {                                   \
    float2 t0 = cadd(A, C), t1 = csub(A, C);                                  \
    float2 t2 = cadd(Bq, D), t3 = csub(Bq, D);                                \
    float2 t3m = make_float2(t3.y, -t3.x);  /* -i*t3 */                       \
    A  = cadd(t0, t2);                                                        \
    Bq = cmulf(cadd(t1, t3m), W1);                                            \
    C  = cmulf(csub(t0, t2), W2);                                             \
    D  = cmulf(csub(t1, t3m), W3);                                            \
} while (0)

// bin->tref-column mapping (col = k ^ 512), as tv[] index: compile-time per p
#define HCOL(p) (((((p) >> 3) & 3)) | ((((p) >> 1) & 3) << 2) | (((((p) & 1)) ^ 1) << 4))

// ---------------- radix-2 smem FFT (hilbert only) ----------------
template <bool INV>
__device__ __forceinline__ void fft1024(float2* sm, const float2* tw, int tid) {
#pragma unroll
    for (int e = 0; e < 4; e++) {
        int i = tid + e * NT;
        int j = __brev(i) >> 22;
        if (i < j) { float2 t = sm[i]; sm[i] = sm[j]; sm[j] = t; }
    }
    __syncthreads();
#pragma unroll
    for (int s = 1; s <= 10; s++) {
        int half = 1 << (s - 1);
#pragma unroll
        for (int e = 0; e < 2; e++) {
            int m   = tid + e * NT;
            int pos = m & (half - 1);
            int i0  = ((m >> (s - 1)) << s) + pos;
            int i1  = i0 + half;
            float2 w = tw[pos << (10 - s)];
            float wy = INV ? -w.y : w.y;
            float2 q = sm[i1];
            float2 v = make_float2(q.x * w.x - q.y * wy, q.x * wy + q.y * w.x);
            float2 u = sm[i0];
            sm[i0] = make_float2(u.x + v.x, u.y + v.y);
            sm[i1] = make_float2(u.x - v.x, u.y - v.y);
        }
        __syncthreads();
    }
    if (INV) {
        const float sc = 1.0f / (float)NN;
#pragma unroll
        for (int e = 0; e < 4; e++) { int i = tid + e * NT; sm[i].x *= sc; sm[i].y *= sc; }
        __syncthreads();
    }
}

// ---------------- kernel 1: init ----------------
__global__ void init_kernel() {
    int t = threadIdx.x;
    if (t < BB) {
        g_accS[t] = 0.0; g_accST[t] = 0.0; g_accT[t] = 0.0; g_accT2[t] = 0.0;
        g_accMax[t] = 0u;
    }
    if (t < 512) {
        double ang = -2.0 * 3.14159265358979323846 * (double)t / (double)NN;
        g_tw[t] = make_float2((float)cos(ang), (float)sin(ang));
    }
}

// ---------------- kernel 2: hilbert + modulation ----------------
__global__ void hilbert_kernel(const float* __restrict__ pred) {
    __shared__ float2 sm[NN];
    __shared__ float2 tw[NN / 2];
    int b = blockIdx.x, tid = threadIdx.x;
#pragma unroll
    for (int e = 0; e < 2; e++) tw[tid + e * NT] = g_tw[tid + e * NT];
#pragma unroll
    for (int e = 0; e < 4; e++) {
        int i = tid + e * NT;
        sm[i] = make_float2(pred[b * NN + i], 0.0f);
    }
    __syncthreads();
    fft1024<false>(sm, tw, tid);
#pragma unroll
    for (int e = 0; e < 4; e++) {
        int i = tid + e * NT;
        float h = (i < NN / 2) ? 0.0f : ((i == NN / 2) ? 1.0f : 2.0f);
        sm[i].x *= h; sm[i].y *= h;
    }
    __syncthreads();
    fft1024<true>(sm, tw, tid);
#pragma unroll
    for (int e = 0; e < 4; e++) {
        int i = tid + e * NT;
        float2 a = sm[i];
        g_pa[b * NN + i] = a;
        float ang = (float)(2.0 * 1175000000000000.0 * 1.5e-15 * (double)(i - 512));
        float cs = cosf(ang), sn = sinf(ang);
        g_pam[b * NN + i] = cmulf(a, make_float2(cs, -sn));
    }
}

// ---------------- kernel 3: MSE partials ----------------
__global__ void mse_kernel(const float* __restrict__ label) {
    int b = blockIdx.x, tid = threadIdx.x;
    const float* lr = label + (size_t)b * 2 * NN;
    const float* li = lr + NN;

    __shared__ int s_frR, s_laR, s_frI, s_laI;
    if (tid == 0) { s_frR = NN; s_laR = -1; s_frI = NN; s_laI = -1; }
    __syncthreads();
    int frR = NN, laR = -1, frI = NN, laI = -1;
    for (int t = tid; t < NN; t += NT) {
        if (fabsf(lr[t]) > 0.01f) { frR = min(frR, t); laR = max(laR, t); }
        if (fabsf(li[t]) > 0.01f) { frI = min(frI, t); laI = max(laI, t); }
    }
    atomicMin(&s_frR, frR); atomicMax(&s_laR, laR);
    atomicMin(&s_frI, frI); atomicMax(&s_laI, laI);
    __syncthreads();
    int fr_r = (s_frR == NN) ? 0 : s_frR;
    int la_r = (s_laR < 0) ? (NN - 1) : s_laR;
    int fr_i = (s_frI == NN) ? 0 : s_frI;
    int la_i = (s_laI < 0) ? (NN - 1) : s_laI;
    int first = min(fr_r, fr_i);
    int last  = max(la_r, la_i);

    float sR = 0, sI = 0, sInt = 0, sPh = 0;
    for (int t = tid; t < NN; t += NT) {
        float2 p = g_pa[b * NN + t];
        float LR = lr[t], LI = li[t];
        bool inr = (t >= first) && (t < last);
        float pm = inr ? 10.0f : 1.0f;
        float dr = p.x - LR, di = p.y - LI;
        float pint = p.x * p.x + p.y * p.y;
        float lint = LR * LR + LI * LI;
        float dint = pint - lint;
        sR   += dr * dr * pm;
        sI   += di * di * pm;
        sInt += dint * dint * pm;
        if (inr) {
            float dp = atan2f(p.y, p.x) - atan2f(LI, LR);
            sPh += dp * dp;
        }
    }
    float tot = sR + sI + sInt + sPh;
#pragma unroll
    for (int o = 16; o > 0; o >>= 1) tot += __shfl_down_sync(0xffffffffu, tot, o);
    __shared__ float rA[8];
    int w = tid >> 5, lane = tid & 31;
    if (lane == 0) rA[w] = tot;
    __syncthreads();
    if (tid == 0) {
        float a = 0;
#pragma unroll
        for (int i = 0; i < 8; i++) a += rA[i];
        g_mse[b] = a * (1.0f / NN) * 0.25f;
    }
}

// ---------------- kernel 4: SHG, warp-autonomous 1024-pt FFT ----------------
// 32 threads per FFT (1 warp), 32 elements/thread, single padded transpose,
// no cross-warp barriers. 8 warps/block, 4 rows/warp, grid (32, BB).
#define TPAD 1056   // 33*32 float2 per warp

__global__ __launch_bounds__(256, 2) void shg_kernel(const float* __restrict__ tref) {
    extern __shared__ char sraw[];
    float2* paS2    = (float2*)sraw;        // 2048 (16KB, duplicated)
    float2* pamS    = paS2 + 2 * NN;        // 1024 (8KB)
    float2* twS     = pamS + NN;            // 512  (4KB)
    float2* tbufAll = twS + 512;            // 8 * 1056 (66KB)

    int tid = threadIdx.x;
    int b = blockIdx.y;
    int wid = tid >> 5, lt = tid & 31;
    float2* tbuf = tbufAll + wid * TPAD;

    for (int i = tid; i < NN; i += NT) {
        float2 v = g_pa[b * NN + i];
        paS2[i] = v; paS2[i + NN] = v;
        pamS[i] = g_pam[b * NN + i];
    }
    for (int i = tid; i < 512; i += NT) twS[i] = g_tw[i];
    __syncthreads();

    const float DT2 = 2.25e-30f;
    const float* base = tref + (size_t)b * NN * NN;
    const int kb = ((lt >> 3) & 3) | (((lt >> 1) & 3) << 2) | ((lt & 1) << 4);

    float lmax = 0.0f;
    double dS = 0.0, dST = 0.0, dT = 0.0, dT2a = 0.0;

    for (int rr = 0; rr < 4; rr++) {
        int d = blockIdx.x * 32 + wid * 4 + rr;   // 0..1023
        int delay = d - 512;
        int tb = (lt - delay) & (NN - 1);

        // tref loads issued first: each instruction's 32 lanes hit one 128B line
        const float* rowp = base + (size_t)d * NN + kb;
        float tv[32];
#pragma unroll
        for (int m = 0; m < 32; m++) tv[m] = rowp[32 * m];

        // input build, layout: r[e] = c[lt + 32e]
        float2 r[32];
#pragma unroll
        for (int e = 0; e < 32; e++)
            r[e] = cmulf(pamS[lt + 32 * e], paS2[tb + 32 * e]);

        // stage A (L=1024, radix-4): quads (e0, e0+8, e0+16, e0+24), q = lt+32e0
#pragma unroll
        for (int e0 = 0; e0 < 8; e0++) {
            float2 w1 = twS[lt + 32 * e0];
            float2 w2 = cmulf(w1, w1), w3 = cmulf(w1, w2);
            BFLY4(r[e0], r[e0 + 8], r[e0 + 16], r[e0 + 24], w1, w2, w3);
        }
        // stage B (L=256, radix-4): quads (8blk+e1, +2, +4, +6), q = lt+32e1
#pragma unroll
        for (int e1 = 0; e1 < 2; e1++) {
            float2 w1 = twS[4 * lt + 128 * e1];
            float2 w2 = cmulf(w1, w1), w3 = cmulf(w1, w2);
#pragma unroll
            for (int blk = 0; blk < 4; blk++) {
                int q0 = 8 * blk + e1;
                BFLY4(r[q0], r[q0 + 2], r[q0 + 4], r[q0 + 6], w1, w2, w3);
            }
        }
        // stage C (L=64, radix-2): pairs (e, e+1), w = W_64^lt = W_1024^{16lt}
        {
            float2 wc = twS[16 * lt];
#pragma unroll
            for (int e = 0; e < 32; e += 2) {
                float2 a = r[e], bq = r[e + 1];
                r[e]     = cadd(a, bq);
                r[e + 1] = cmulf(csub(a, bq), wc);
            }
        }
        // transpose (padded, conflict-free): pos t stored at 33*(t&31) + (t>>5)
#pragma unroll
        for (int e = 0; e < 32; e++) tbuf[33 * lt + e] = r[e];
        __syncwarp();
#pragma unroll
        for (int p = 0; p < 32; p++) r[p] = tbuf[33 * p + lt];
        __syncwarp();

        // stage D (L=32, radix-4): constant twiddles W_32
        {
            const float2 WD1[8] = {{1.f,0.f},{0.98078528f,-0.19509032f},{0.92387953f,-0.38268343f},{0.83146961f,-0.55557023f},{0.70710678f,-0.70710678f},{0.55557023f,-0.83146961f},{0.38268343f,-0.92387953f},{0.19509032f,-0.98078528f}};
            const float2 WD2[8] = {{1.f,0.f},{0.92387953f,-0.38268343f},{0.70710678f,-0.70710678f},{0.38268343f,-0.92387953f},{0.f,-1.f},{-0.38268343f,-0.92387953f},{-0.70710678f,-0.70710678f},{-0.92387953f,-0.38268343f}};
            const float2 WD3[8] = {{1.f,0.f},{0.83146961f,-0.55557023f},{0.38268343f,-0.92387953f},{-0.19509032f,-0.98078528f},{-0.70710678f,-0.70710678f},{-0.98078528f,-0.19509032f},{-0.92387953f,0.38268343f},{-0.55557023f,0.83146961f}};
#pragma unroll
            for (int p0 = 0; p0 < 8; p0++)
                BFLY4(r[p0], r[p0 + 8], r[p0 + 16], r[p0 + 24], WD1[p0], WD2[p0], WD3[p0]);
        }
        // stage E (L=8, radix-4): q in {0,1}; q=0 identity twiddles (folded)
        {
            const float2 ONE = {1.f, 0.f};
            const float2 WE1 = {0.70710678f, -0.70710678f};
            const float2 WE2 = {0.f, -1.f};
            const float2 WE3 = {-0.70710678f, -0.70710678f};
#pragma unroll
            for (int pb = 0; pb < 32; pb += 8) {
                BFLY4(r[pb + 0], r[pb + 2], r[pb + 4], r[pb + 6], ONE, ONE, ONE);
                BFLY4(r[pb + 1], r[pb + 3], r[pb + 5], r[pb + 7], WE1, WE2, WE3);
            }
        }
        // stage F (L=2) + magnitudes + fused reductions
        float rS = 0.0f, rST = 0.0f;
#pragma unroll
        for (int h = 0; h < 16; h++) {
            float2 a = r[2 * h], bq = r[2 * h + 1];
            float2 y0 = cadd(a, bq);
            float2 y1 = csub(a, bq);
            float s0 = (y0.x * y0.x + y0.y * y0.y) * DT2;
            float s1 = (y1.x * y1.x + y1.y * y1.y) * DT2;
            lmax = fmaxf(lmax, fmaxf(s0, s1));
            rS += s0 + s1;
            rST += s0 * tv[HCOL(2 * h)] + s1 * tv[HCOL(2 * h + 1)];
        }
        float rT = 0.0f, rT2 = 0.0f;
#pragma unroll
        for (int m = 0; m < 32; m++) { rT += tv[m]; rT2 += tv[m] * tv[m]; }

        dS += rS; dST += rST; dT += rT; dT2a += rT2;
    }

    // block reduction
    double vS = dS, vST = dST, vT = dT, vT2 = dT2a; float vM = lmax;
#pragma unroll
    for (int o = 16; o > 0; o >>= 1) {
        vS  += __shfl_down_sync(0xffffffffu, vS,  o);
        vST += __shfl_down_sync(0xffffffffu, vST, o);
        vT  += __shfl_down_sync(0xffffffffu, vT,  o);
        vT2 += __shfl_down_sync(0xffffffffu, vT2, o);
        vM   = fmaxf(vM, __shfl_down_sync(0xffffffffu, vM, o));
    }
    __shared__ double sS[8], sST[8], sT[8], sT2[8];
    __shared__ float  sM[8];
    if (lt == 0) { sS[wid] = vS; sST[wid] = vST; sT[wid] = vT; sT2[wid] = vT2; sM[wid] = vM; }
    __syncthreads();
    if (tid == 0) {
        double aS = 0, aST = 0, aT = 0, aT2 = 0; float aM = 0.0f;
#pragma unroll
        for (int i = 0; i < 8; i++) {
            aS += sS[i]; aST += sST[i]; aT += sT[i]; aT2 += sT2[i];
            aM = fmaxf(aM, sM[i]);
        }
        atomicAdd(&g_accS[b],  aS);
        atomicAdd(&g_accST[b], aST);
        atomicAdd(&g_accT[b],  aT);
        atomicAdd(&g_accT2[b], aT2);
        atomicMax(&g_accMax[b], __float_as_uint(aM));
    }
}

// ---------------- kernel 5: frog + final mean ----------------
__global__ void finalize_kernel(float* out) {
    int b = threadIdx.x;   // 32 threads
    double M    = (double)__uint_as_float(g_accMax[b]);
    double sum1 = g_accST[b] / M;
    double mu   = sum1 / g_accT2[b];
    double diff = g_accS[b] / M - mu * g_accT[b];
    double r2   = diff * diff;
    float frog  = (r2 == 0.0) ? 0.0f : (float)(sqrt(r2) / (double)NN);
    float v = g_mse[b] + frog;
#pragma unroll
    for (int o = 16; o > 0; o >>= 1) v += __shfl_down_sync(0xffffffffu, v, o);
    if (b == 0) out[0] = v * (1.0f / BB);
}

// ---------------- launch ----------------
extern "C" void kernel_launch(void* const* d_in, const int* in_sizes, int n_in,
                              void* d_out, int out_size) {
    const float* pred  = (const float*)d_in[0];
    const float* label = (const float*)d_in[1];
    const float* shg   = (const float*)d_in[2];
    float* out = (float*)d_out;

    const int SHG_SMEM = (2 * NN + NN + 512 + 8 * TPAD) * sizeof(float2);  // ~94KB
    static int attr_done = 0;
    if (!attr_done) {
        cudaFuncSetAttribute(shg_kernel, cudaFuncAttributeMaxDynamicSharedMemorySize, SHG_SMEM);
        attr_done = 1;
    }

    init_kernel<<<1, 512>>>();
    hilbert_kernel<<<BB, NT>>>(pred);
    mse_kernel<<<BB, NT>>>(label);
    shg_kernel<<<dim3(32, BB), NT, SHG_SMEM>>>(shg);   // node 4 -> ncu capture slot
    finalize_kernel<<<1, 32>>>(out);
}